// round 3
// baseline (speedup 1.0000x reference)
#include <cuda_runtime.h>
#include <cstdint>

// Shapes (fixed by the problem)
#define B_ 2
#define S_ 1024
#define H_ 512
#define A_ 128

#define CTAS_PER_B 74            // 148 CTAs total, 13-14 rows each
#define MAXR 16                  // padded row capacity for smem
#define TJ 128

// ---------------- scratch (no allocation allowed) ----------------
__device__ float g_wx [B_ * S_ * A_];        // [m=b*S+s][a]  row-major (1 MB)
__device__ float g_uxt[B_ * A_ * S_];        // [b][a][s]     a-major / transposed (1 MB)

__device__ __forceinline__ float tanh_fast(float x) {
    float y;
    asm("tanh.approx.f32 %0, %1;" : "=f"(y) : "f"(x));
    return y;
}

// ---------------- kernel 0: zero context region ----------------
__global__ void zero_kernel(float* ctx) {
    int t = blockIdx.x * blockDim.x + threadIdx.x;
    if (t < B_ * H_) ctx[t] = 0.0f;
}

// ---------------- kernel 1: wx = lstm@w (row-major), uxt = (lstm@u)^T ----------------
#define BM 64
#define BN 64
#define BK 16
__global__ __launch_bounds__(256) void gemm_wxux(
    const float* __restrict__ lstm, const float* __restrict__ w, const float* __restrict__ u)
{
    __shared__ float As[BK][BM];
    __shared__ float Bs[BK][BN];
    int tid = threadIdx.x;
    int m0 = blockIdx.x * BM;                  // 32 blocks (m = b*S+s)
    int n0 = blockIdx.y * BN;                  // 4 blocks: 0,64 -> w ; 128,192 -> u
    const float* bsrc = (n0 < A_) ? (w + n0) : (u + (n0 - A_));

    int tm = (tid >> 4) * 4;
    int tn = (tid & 15) * 4;
    int la_m = tid >> 2;
    int la_k = (tid & 3) * 4;
    int lb_k = tid >> 4;
    int lb_n = (tid & 15) * 4;

    float acc[4][4];
#pragma unroll
    for (int i = 0; i < 4; i++)
#pragma unroll
        for (int j = 0; j < 4; j++) acc[i][j] = 0.0f;

    for (int k0 = 0; k0 < H_; k0 += BK) {
        float4 av = *(const float4*)(lstm + (size_t)(m0 + la_m) * H_ + k0 + la_k);
        float4 bv = *(const float4*)(bsrc + (size_t)(k0 + lb_k) * A_ + lb_n);
        __syncthreads();
        As[la_k + 0][la_m] = av.x;
        As[la_k + 1][la_m] = av.y;
        As[la_k + 2][la_m] = av.z;
        As[la_k + 3][la_m] = av.w;
        *(float4*)&Bs[lb_k][lb_n] = bv;
        __syncthreads();
#pragma unroll
        for (int kk = 0; kk < BK; kk++) {
            float4 a4 = *(const float4*)&As[kk][tm];
            float4 b4 = *(const float4*)&Bs[kk][tn];
            float am[4] = {a4.x, a4.y, a4.z, a4.w};
            float bn[4] = {b4.x, b4.y, b4.z, b4.w};
#pragma unroll
            for (int i = 0; i < 4; i++)
#pragma unroll
                for (int j = 0; j < 4; j++) acc[i][j] = fmaf(am[i], bn[j], acc[i][j]);
        }
    }

    if (n0 < A_) {
#pragma unroll
        for (int i = 0; i < 4; i++) {
            float4 o = make_float4(acc[i][0], acc[i][1], acc[i][2], acc[i][3]);
            *(float4*)(g_wx + (size_t)(m0 + tm + i) * A_ + n0 + tn) = o;
        }
    } else {
        int b  = m0 / S_;
        int s0 = (m0 % S_) + tm;
        int a0 = (n0 - A_) + tn;
        float* base = g_uxt + (size_t)b * A_ * S_;
#pragma unroll
        for (int j = 0; j < 4; j++) {
            float4 o = make_float4(acc[0][j], acc[1][j], acc[2][j], acc[3][j]);
            *(float4*)(base + (size_t)(a0 + j) * S_ + s0) = o;
        }
    }
}

// ---------------- kernel 2: e = tanh-sum, register softmax, attn write ----------------
// dyn smem: wx_s[MAXR][128] + ux_s[128][TJ] + v_s[128]  ~ 74.3 KB. 148 balanced CTAs.
__global__ __launch_bounds__(512) void attn_e_kernel(
    const float* __restrict__ v, float* __restrict__ attn_out)
{
    extern __shared__ float sm[];
    float* wx_s = sm;                          // MAXR*128
    float* ux_s = wx_s + MAXR * A_;            // 128*TJ (a-major)
    float* v_s  = ux_s + A_ * TJ;              // 128

    int tid  = threadIdx.x;
    int warp = tid >> 5;                       // warp r handles row i0+r
    int lane = tid & 31;
    int blk  = blockIdx.x;                     // 148 blocks
    int b    = blk / CTAS_PER_B;
    int t    = blk % CTAS_PER_B;
    int i0   = (S_ * t) / CTAS_PER_B;          // balanced 13-14 rows, within batch b
    int i1   = (S_ * (t + 1)) / CTAS_PER_B;
    int nr   = i1 - i0;

    // stage wx rows (nr x 128) + v
    for (int x = tid; x < nr * (A_ / 4); x += 512) {
        int r = x >> 5, c = x & 31;
        *(float4*)(wx_s + r * A_ + 4 * c) =
            *(const float4*)(g_wx + (size_t)(b * S_ + i0 + r) * A_ + 4 * c);
    }
    if (tid < 32) ((float4*)v_s)[tid] = ((const float4*)v)[tid];

    const float* uxt_b = g_uxt + (size_t)b * A_ * S_;
    bool active = (warp < nr);

    float er[32];                              // full e row, register-resident

    for (int jt = 0; jt < S_; jt += TJ) {
        __syncthreads();                       // protect ux_s reuse
        for (int x = tid; x < A_ * (TJ / 4); x += 512) {
            int a = x >> 5, c = x & 31;
            *(float4*)(ux_s + a * TJ + 4 * c) =
                *(const float4*)(uxt_b + (size_t)a * S_ + jt + 4 * c);
        }
        __syncthreads();

        if (active) {
            float acc0 = 0.f, acc1 = 0.f, acc2 = 0.f, acc3 = 0.f;
            const float4* wr = (const float4*)(wx_s + warp * A_);
            const float4* vr = (const float4*)v_s;
            const float*  ub = ux_s + 4 * lane;
#pragma unroll 8
            for (int a4 = 0; a4 < A_ / 4; a4++) {
                float4 w4 = wr[a4];
                float4 v4 = vr[a4];
#define DO(c, k) { \
                float4 uu = *(const float4*)(ub + (4 * a4 + k) * TJ); \
                float wc = w4.c, vc = v4.c; \
                acc0 = fmaf(tanh_fast(wc + uu.x), vc, acc0); \
                acc1 = fmaf(tanh_fast(wc + uu.y), vc, acc1); \
                acc2 = fmaf(tanh_fast(wc + uu.z), vc, acc2); \
                acc3 = fmaf(tanh_fast(wc + uu.w), vc, acc3); }
                DO(x, 0) DO(y, 1) DO(z, 2) DO(w, 3)
#undef DO
            }
            int ti = jt >> 7;                  // tile index 0..7
            er[4 * ti + 0] = acc0;
            er[4 * ti + 1] = acc1;
            er[4 * ti + 2] = acc2;
            er[4 * ti + 3] = acc3;
        }
    }

    if (active) {
        // register softmax: row max
        float m = er[0];
#pragma unroll
        for (int k = 1; k < 32; k++) m = fmaxf(m, er[k]);
#pragma unroll
        for (int o = 16; o; o >>= 1) m = fmaxf(m, __shfl_xor_sync(0xffffffffu, m, o));
        float s = 0.f;
#pragma unroll
        for (int k = 0; k < 32; k++) {
            er[k] = __expf(er[k] - m);
            s += er[k];
        }
#pragma unroll
        for (int o = 16; o; o >>= 1) s += __shfl_xor_sync(0xffffffffu, s, o);
        float inv = 1.0f / s;
        float* orow = attn_out + (size_t)(b * S_ + i0 + warp) * S_;
#pragma unroll
        for (int ti = 0; ti < 8; ti++) {
            float4 o = make_float4(er[4 * ti] * inv, er[4 * ti + 1] * inv,
                                   er[4 * ti + 2] * inv, er[4 * ti + 3] * inv);
            *(float4*)(orow + ti * TJ + 4 * lane) = o;
        }
    }
}

// ---------------- kernel 3: colsum from attn (L2) + context GEMV ----------------
__global__ __launch_bounds__(512) void context_kernel(
    const float* __restrict__ lstm, const float* __restrict__ attn, float* __restrict__ ctx)
{
    int b  = blockIdx.x >> 4;                  // 32 blocks: 2 b x 16 j-chunks
    int j0 = (blockIdx.x & 15) * 64;
    int tid = threadIdx.x;
    __shared__ float csp[8][64];
    __shared__ float cs[64];

    int jj = tid & 63, ig = tid >> 6;          // 8 i-groups x 64 j
    float s = 0.f;
    const float* ap = attn + (size_t)(b * S_ + ig) * S_ + j0 + jj;
#pragma unroll 8
    for (int i = ig; i < S_; i += 8) {
        s += *ap;
        ap += 8 * S_;
    }
    csp[ig][jj] = s;
    __syncthreads();
    if (tid < 64) {
        float tt = 0.f;
#pragma unroll
        for (int r = 0; r < 8; r++) tt += csp[r][tid];
        cs[tid] = tt;
    }
    __syncthreads();

    int h = tid;                               // 512 threads = H
    float acc = 0.f;
    const float* lp = lstm + (size_t)(b * S_ + j0) * H_ + h;
#pragma unroll 8
    for (int j = 0; j < 64; j++) acc = fmaf(cs[j], lp[(size_t)j * H_], acc);
    atomicAdd(&ctx[b * H_ + h], acc);
}

// ---------------- launch ----------------
extern "C" void kernel_launch(void* const* d_in, const int* in_sizes, int n_in,
                              void* d_out, int out_size)
{
    const float* lstm = (const float*)d_in[0];
    const float* w    = (const float*)d_in[1];
    const float* u    = (const float*)d_in[2];
    const float* v    = (const float*)d_in[3];
    float* out  = (float*)d_out;
    float* ctx  = out;                // (B,H) = 1024 floats first
    float* attn = out + B_ * H_;      // (B,S,S) = 2M floats after

    zero_kernel<<<2, 512>>>(ctx);
    gemm_wxux<<<dim3(32, 4), 256>>>(lstm, w, u);

    size_t smem = (size_t)(MAXR * A_ + A_ * TJ + A_) * sizeof(float); // ~74.5 KB
    cudaFuncSetAttribute(attn_e_kernel, cudaFuncAttributeMaxDynamicSharedMemorySize, (int)smem);
    attn_e_kernel<<<B_ * CTAS_PER_B, 512, smem>>>(v, attn);

    context_kernel<<<B_ * 16, 512>>>(lstm, attn, ctx);
}

// round 4
// speedup vs baseline: 1.1031x; 1.1031x over previous
#include <cuda_runtime.h>
#include <cstdint>

// Shapes (fixed by the problem)
#define B_ 2
#define S_ 1024
#define H_ 512
#define A_ 128

#define CTAS_PER_B 74            // 148 CTAs total, 13-14 rows each
#define MAXR 16
#define TJ 128
#define NT 8                     // S_/TJ tiles

// ---------------- scratch (no allocation allowed) ----------------
__device__ float g_wx [B_ * S_ * A_];        // [m=b*S+s][a]  row-major (1 MB)
__device__ float g_uxt[B_ * A_ * S_];        // [b][a][s]     a-major / transposed (1 MB)
__device__ float g_colsum[B_ * S_];

__device__ __forceinline__ float tanh_fast(float x) {
    float y;
    asm("tanh.approx.f32 %0, %1;" : "=f"(y) : "f"(x));
    return y;
}

__device__ __forceinline__ void cp16(float* dst_smem, const float* src) {
    uint32_t d = (uint32_t)__cvta_generic_to_shared(dst_smem);
    asm volatile("cp.async.cg.shared.global [%0], [%1], 16;\n" :: "r"(d), "l"(src));
}
#define CP_COMMIT() asm volatile("cp.async.commit_group;\n")
#define CP_WAIT(N)  asm volatile("cp.async.wait_group %0;\n" :: "n"(N))

// ---------------- kernel 0: zero colsum + context ----------------
__global__ void zero_kernel(float* ctx) {
    int t = blockIdx.x * blockDim.x + threadIdx.x;
    if (t < B_ * S_) g_colsum[t] = 0.0f;
    if (t < B_ * H_) ctx[t] = 0.0f;
}

// ---------------- kernel 1: wx = lstm@w (row-major), uxt = (lstm@u)^T ----------------
#define BM 64
#define BN 64
#define BK 16
__global__ __launch_bounds__(256) void gemm_wxux(
    const float* __restrict__ lstm, const float* __restrict__ w, const float* __restrict__ u)
{
    __shared__ float As[BK][BM];
    __shared__ float Bs[BK][BN];
    int tid = threadIdx.x;
    int m0 = blockIdx.x * BM;
    int n0 = blockIdx.y * BN;                  // 0,64 -> w ; 128,192 -> u
    const float* bsrc = (n0 < A_) ? (w + n0) : (u + (n0 - A_));

    int tm = (tid >> 4) * 4;
    int tn = (tid & 15) * 4;
    int la_m = tid >> 2;
    int la_k = (tid & 3) * 4;
    int lb_k = tid >> 4;
    int lb_n = (tid & 15) * 4;

    float acc[4][4];
#pragma unroll
    for (int i = 0; i < 4; i++)
#pragma unroll
        for (int j = 0; j < 4; j++) acc[i][j] = 0.0f;

    for (int k0 = 0; k0 < H_; k0 += BK) {
        float4 av = *(const float4*)(lstm + (size_t)(m0 + la_m) * H_ + k0 + la_k);
        float4 bv = *(const float4*)(bsrc + (size_t)(k0 + lb_k) * A_ + lb_n);
        __syncthreads();
        As[la_k + 0][la_m] = av.x;
        As[la_k + 1][la_m] = av.y;
        As[la_k + 2][la_m] = av.z;
        As[la_k + 3][la_m] = av.w;
        *(float4*)&Bs[lb_k][lb_n] = bv;
        __syncthreads();
#pragma unroll
        for (int kk = 0; kk < BK; kk++) {
            float4 a4 = *(const float4*)&As[kk][tm];
            float4 b4 = *(const float4*)&Bs[kk][tn];
            float am[4] = {a4.x, a4.y, a4.z, a4.w};
            float bn[4] = {b4.x, b4.y, b4.z, b4.w};
#pragma unroll
            for (int i = 0; i < 4; i++)
#pragma unroll
                for (int j = 0; j < 4; j++) acc[i][j] = fmaf(am[i], bn[j], acc[i][j]);
        }
    }

    if (n0 < A_) {
#pragma unroll
        for (int i = 0; i < 4; i++) {
            float4 o = make_float4(acc[i][0], acc[i][1], acc[i][2], acc[i][3]);
            *(float4*)(g_wx + (size_t)(m0 + tm + i) * A_ + n0 + tn) = o;
        }
    } else {
        int b  = m0 / S_;
        int s0 = (m0 % S_) + tm;
        int a0 = (n0 - A_) + tn;
        float* base = g_uxt + (size_t)b * A_ * S_;
#pragma unroll
        for (int j = 0; j < 4; j++) {
            float4 o = make_float4(acc[0][j], acc[1][j], acc[2][j], acc[3][j]);
            *(float4*)(base + (size_t)(a0 + j) * S_ + s0) = o;
        }
    }
}

// ---------------- kernel 2: e = tanh-sum, register softmax, attn + colsum ----------------
// dyn smem: wx_s[16][128] + ux double buffer 2*[128][TJ] + v_s[128]  ~ 139.8 KB
__global__ __launch_bounds__(512) void attn_e_kernel(
    const float* __restrict__ v, float* __restrict__ attn_out)
{
    extern __shared__ float sm[];
    float* wx_s = sm;                          // MAXR*128
    float* ux0  = wx_s + MAXR * A_;            // 128*TJ buffer 0
    float* ux1  = ux0 + A_ * TJ;               // 128*TJ buffer 1
    float* v_s  = ux1 + A_ * TJ;               // 128

    int tid  = threadIdx.x;
    int warp = tid >> 5;
    int lane = tid & 31;
    int blk  = blockIdx.x;
    int b    = blk / CTAS_PER_B;
    int t_   = blk % CTAS_PER_B;
    int i0   = (S_ * t_) / CTAS_PER_B;
    int i1   = (S_ * (t_ + 1)) / CTAS_PER_B;
    int nr   = i1 - i0;                        // 13 or 14

    const float* uxt_b = g_uxt + (size_t)b * A_ * S_;
    int pa = tid >> 5, pc = tid & 31;          // prefetch coords: 8 rows per thread

    // async-prefetch tile 0 into ux0
#pragma unroll
    for (int k = 0; k < 8; k++)
        cp16(ux0 + (pa + 16 * k) * TJ + 4 * pc, uxt_b + (size_t)(pa + 16 * k) * S_ + 4 * pc);
    CP_COMMIT();

    // stage wx rows + v (plain loads, covered by first syncthreads)
    for (int x = tid; x < nr * (A_ / 4); x += 512) {
        int r = x >> 5, c = x & 31;
        *(float4*)(wx_s + r * A_ + 4 * c) =
            *(const float4*)(g_wx + (size_t)(b * S_ + i0 + r) * A_ + 4 * c);
    }
    if (tid < 32) ((float4*)v_s)[tid] = ((const float4*)v)[tid];

    bool active = (warp < nr);
    float er[4 * NT];                          // full e row in registers

#pragma unroll
    for (int t = 0; t < NT; t++) {
        float* cur = (t & 1) ? ux1 : ux0;
        if (t + 1 < NT) {                      // prefetch next tile
            float* nxt = ((t + 1) & 1) ? ux1 : ux0;
            const float* src = uxt_b + (size_t)(t + 1) * TJ;
#pragma unroll
            for (int k = 0; k < 8; k++)
                cp16(nxt + (pa + 16 * k) * TJ + 4 * pc, src + (size_t)(pa + 16 * k) * S_ + 4 * pc);
            CP_COMMIT();
            CP_WAIT(1);                        // tile t has landed
        } else {
            CP_WAIT(0);
        }
        __syncthreads();

        if (active) {
            float acc0 = 0.f, acc1 = 0.f, acc2 = 0.f, acc3 = 0.f;
            const float4* wr = (const float4*)(wx_s + warp * A_);
            const float4* vr = (const float4*)v_s;
            const float*  ub = cur + 4 * lane;
#pragma unroll 8
            for (int a4 = 0; a4 < A_ / 4; a4++) {
                float4 w4 = wr[a4];
                float4 v4 = vr[a4];
#define DO(c, k) { \
                float4 uu = *(const float4*)(ub + (4 * a4 + k) * TJ); \
                float wc = w4.c, vc = v4.c; \
                acc0 = fmaf(tanh_fast(wc + uu.x), vc, acc0); \
                acc1 = fmaf(tanh_fast(wc + uu.y), vc, acc1); \
                acc2 = fmaf(tanh_fast(wc + uu.z), vc, acc2); \
                acc3 = fmaf(tanh_fast(wc + uu.w), vc, acc3); }
                DO(x, 0) DO(y, 1) DO(z, 2) DO(w, 3)
#undef DO
            }
            er[4 * t + 0] = acc0;
            er[4 * t + 1] = acc1;
            er[4 * t + 2] = acc2;
            er[4 * t + 3] = acc3;
        }
        __syncthreads();                       // compute done before buffer reuse
    }

    // register softmax + write attn + stash scaled row into smem slot
    float* slots = ux0;                        // 32768 floats free now; slot w = slots + w*S_
    if (active) {
        float m = er[0];
#pragma unroll
        for (int k = 1; k < 4 * NT; k++) m = fmaxf(m, er[k]);
#pragma unroll
        for (int o = 16; o; o >>= 1) m = fmaxf(m, __shfl_xor_sync(0xffffffffu, m, o));
        float s = 0.f;
#pragma unroll
        for (int k = 0; k < 4 * NT; k++) {
            er[k] = __expf(er[k] - m);
            s += er[k];
        }
#pragma unroll
        for (int o = 16; o; o >>= 1) s += __shfl_xor_sync(0xffffffffu, s, o);
        float inv = 1.0f / s;
        float* orow = attn_out + (size_t)(b * S_ + i0 + warp) * S_;
        float* srow = slots + (size_t)warp * S_;
#pragma unroll
        for (int ti = 0; ti < NT; ti++) {
            float4 o = make_float4(er[4 * ti] * inv, er[4 * ti + 1] * inv,
                                   er[4 * ti + 2] * inv, er[4 * ti + 3] * inv);
            *(float4*)(orow + ti * TJ + 4 * lane) = o;
            *(float4*)(srow + ti * TJ + 4 * lane) = o;
        }
    }
    __syncthreads();

    // reduce slots over rows -> global colsum (1024 atomics per CTA)
    for (int j = tid; j < S_; j += 512) {
        float s = 0.f;
        for (int r = 0; r < nr; r++) s += slots[(size_t)r * S_ + j];
        atomicAdd(&g_colsum[b * S_ + j], s);
    }
}

// ---------------- kernel 3: context[b,h] = sum_j colsum[b,j] * lstm[b,j,h] ----------------
__global__ __launch_bounds__(512) void context_kernel(
    const float* __restrict__ lstm, float* __restrict__ ctx)
{
    int b  = blockIdx.x >> 6;                  // 2 * 64 blocks
    int j0 = (blockIdx.x & 63) * 16;
    int h  = threadIdx.x;
    __shared__ float cs[16];
    if (threadIdx.x < 16) cs[threadIdx.x] = g_colsum[b * S_ + j0 + threadIdx.x];
    __syncthreads();
    float acc = 0.f;
    const float* lp = lstm + ((size_t)(b * S_ + j0)) * H_ + h;
#pragma unroll
    for (int j = 0; j < 16; j++) acc = fmaf(cs[j], lp[(size_t)j * H_], acc);
    atomicAdd(&ctx[b * H_ + h], acc);
}

// ---------------- launch ----------------
extern "C" void kernel_launch(void* const* d_in, const int* in_sizes, int n_in,
                              void* d_out, int out_size)
{
    const float* lstm = (const float*)d_in[0];
    const float* w    = (const float*)d_in[1];
    const float* u    = (const float*)d_in[2];
    const float* v    = (const float*)d_in[3];
    float* out  = (float*)d_out;
    float* ctx  = out;                // (B,H) = 1024 floats first
    float* attn = out + B_ * H_;      // (B,S,S) = 2M floats after

    zero_kernel<<<8, 256>>>(ctx);
    gemm_wxux<<<dim3(32, 4), 256>>>(lstm, w, u);

    size_t smem = (size_t)(MAXR * A_ + 2 * A_ * TJ + A_) * sizeof(float); // ~139.8 KB
    cudaFuncSetAttribute(attn_e_kernel, cudaFuncAttributeMaxDynamicSharedMemorySize, (int)smem);
    attn_e_kernel<<<B_ * CTAS_PER_B, 512, smem>>>(v, attn);

    context_kernel<<<B_ * 64, 512>>>(lstm, ctx);
}